// round 6
// baseline (speedup 1.0000x reference)
#include <cuda_runtime.h>
#include <cstdint>

#define TH 1.0f
#define EPS_BN 1e-5f

// scratch (no allocations allowed -> device globals)
__device__ float g_dm[256 * 256];
__device__ int   g_rowok[256];
__device__ int   g_done = 0;   // reset to 0 by the last block each run (replay-safe)

// ---------------------------------------------------------------------------
// Single fused kernel, 3072 blocks x 256 threads:
//  blocks 0..1023 : dm row n = b>>2, slice s = b&3. Thread m computes
//    dm[n][m]; float4s are assembled in registers via warp shuffles (no
//    shared staging) and each thread stores 8 t-copies into dist_mat_full
//    (slice covers t in [s*32, s*32+32)). Slice 0 stores g_dm row + rowok[n]
//    and joins a done-counter; the LAST slice-0 block computes group_indices
//    in-kernel (fast path all-zeros; exact lax.scan replica fallback).
//  blocks 1024..3071 : float4 slab copy v_rel -> v_grouped
//    (stop_gradient(v - v_soft) + v_soft == v exactly).
// Plain stores (no __stcs): output stays resident in the 126MB L2.
// ---------------------------------------------------------------------------
__global__ void fused_kernel(const float* __restrict__ v,
                             const float* __restrict__ w1,
                             const float* __restrict__ b1,
                             const float* __restrict__ bn_gamma,
                             const float* __restrict__ bn_beta,
                             const float* __restrict__ bn_mean,
                             const float* __restrict__ bn_var,
                             const float* __restrict__ w2,
                             const float* __restrict__ b2,
                             float* __restrict__ out) {
    int b = blockIdx.x;
    int tid = threadIdx.x;

    if (b >= 1024) {
        // ---- copy part: v_grouped = v_rel (2M float4 over 2048 blocks) ----
        const float4* __restrict__ v4 = (const float4*)v;
        float4* __restrict__ ov = (float4*)out;
        int i0 = (b - 1024) * 1024 + tid;
        float4 r0 = v4[i0];
        float4 r1 = v4[i0 + 256];
        float4 r2 = v4[i0 + 512];
        float4 r3 = v4[i0 + 768];
        ov[i0]       = r0;
        ov[i0 + 256] = r1;
        ov[i0 + 512] = r2;
        ov[i0 + 768] = r3;
        return;
    }

    // ---- dm + dist broadcast part ----
    __shared__ float sa[32], sw0[32], sw1[32], sb[32];
    __shared__ float sK;
    __shared__ int s_islast;
    if (tid < 32) {
        float scale = bn_gamma[tid] * rsqrtf(bn_var[tid] + EPS_BN);
        float w2o = w2[tid];
        sa[tid]  = w2o * scale;
        sw0[tid] = w1[tid * 2 + 0];
        sw1[tid] = w1[tid * 2 + 1];
        sb[tid]  = b1[tid];
        float kpart = w2o * (bn_beta[tid] - bn_mean[tid] * scale);
        #pragma unroll
        for (int off = 16; off > 0; off >>= 1)
            kpart += __shfl_down_sync(0xffffffffu, kpart, off);
        if (tid == 0) sK = kpart + b2[0];
    }
    __syncthreads();

    int n = b >> 2;
    int s = b & 3;
    int m = tid;
    int lane = tid & 31;
    int w = tid >> 5;
    // x[c][i] = v_rel[0, c, 127, i], layout (1,256,128,256)
    const int base = 127 * 256;
    float d0 = v[base + n] - v[base + m];
    float d1 = v[32768 + base + n] - v[32768 + base + m];

    float sp = sK, sn = sK;
    #pragma unroll
    for (int o = 0; o < 32; o++) {
        float lin = sw0[o] * d0 + sw1[o] * d1;
        sp += sa[o] * fmaxf(lin + sb[o], 0.0f);
        sn += sa[o] * fmaxf(sb[o] - lin, 0.0f);
    }
    float val = 0.5f * (expf(sp) + expf(sn));

    int anyok = __syncthreads_or((m < n) && (val <= TH));
    if (s == 0) {
        g_dm[n * 256 + m] = val;
        if (tid == 0) g_rowok[n] = anyok;
    }

    // assemble float4 for this lane's 4-group via shuffles (no shared):
    // group gbase = lane & ~3 holds m values 32w+gbase .. +3
    int gbase = lane & ~3;
    float4 f;
    f.x = __shfl_sync(0xffffffffu, val, gbase + 0);
    f.y = __shfl_sync(0xffffffffu, val, gbase + 1);
    f.z = __shfl_sync(0xffffffffu, val, gbase + 2);
    f.w = __shfl_sync(0xffffffffu, val, gbase + 3);
    int q = w * 8 + (lane >> 2);        // float4 column 0..63 of the row

    // each lane writes 8 t-copies: t = s*32 + (lane&3) + 4k
    float4* __restrict__ dst = (float4*)(out + 8388864);
    int t0 = s * 32 + (lane & 3);
    long ofs = (long)t0 * 16384 + n * 64 + q;
    #pragma unroll
    for (int k = 0; k < 8; k++)
        dst[ofs + (long)k * 4 * 16384] = f;

    if (s != 0) return;

    // ---- done-counter handshake: last slice-0 block computes groups ----
    if (tid == 0) {
        __threadfence();                       // commit g_dm row + rowok
        int old = atomicAdd(&g_done, 1);
        s_islast = (old == 255);
    }
    __syncthreads();
    if (!s_islast) return;
    __threadfence();                           // see all rows' writes

    float* __restrict__ out_gi = out + 8388608;
    int rowok = g_rowok[tid];
    bool fast = __syncthreads_and(tid == 0 || rowok);
    if (fast) {
        // every row r>=1 merges into the component labeled 0 -> all ranks 0
        out_gi[tid] = 0.0f;
    } else {
        // ---- exact fallback: row-parallel replica of reference lax.scan ----
        __shared__ int comp[256];
        __shared__ int firstidx[256];
        __shared__ int marked[256];
        __shared__ int cstar;
        __shared__ int newcomp;
        comp[tid] = tid;
        __syncthreads();

        for (int r = 1; r < 256; r++) {
            firstidx[tid] = 0x7fffffff;
            marked[tid] = 0;
            if (tid == 0) cstar = -1;
            __syncthreads();

            int myc = comp[tid];
            int rcomp = comp[r];
            bool okc = (tid < r) && (g_dm[r * 256 + tid] <= TH);
            if (okc) {
                atomicMin(&firstidx[myc], tid);
                marked[myc] = 1;
            }
            if (tid == r) marked[myc] = 1;
            __syncthreads();

            if (okc && myc != rcomp && firstidx[myc] == tid)
                atomicMax(&cstar, tid);
            __syncthreads();

            int cs = cstar;
            if (cs >= 0 && tid == cs) newcomp = myc;
            __syncthreads();
            if (cs >= 0 && marked[myc]) comp[tid] = newcomp;
            __syncthreads();
        }

        __shared__ int pres[256];
        pres[tid] = 0;
        __syncthreads();
        pres[comp[tid]] = 1;
        __syncthreads();
        for (int off = 1; off < 256; off <<= 1) {
            int t = (tid >= off) ? pres[tid - off] : 0;
            __syncthreads();
            pres[tid] += t;
            __syncthreads();
        }
        out_gi[tid] = (float)(pres[comp[tid]] - 1);
    }
    __syncthreads();
    if (tid == 0) g_done = 0;                  // reset for next graph replay
}

extern "C" void kernel_launch(void* const* d_in, const int* in_sizes, int n_in,
                              void* d_out, int out_size) {
    const float* v_rel    = (const float*)d_in[0];
    const float* w1       = (const float*)d_in[1];
    const float* b1       = (const float*)d_in[2];
    const float* bn_gamma = (const float*)d_in[3];
    const float* bn_beta  = (const float*)d_in[4];
    const float* bn_mean  = (const float*)d_in[5];
    const float* bn_var   = (const float*)d_in[6];
    const float* w2       = (const float*)d_in[7];
    const float* b2       = (const float*)d_in[8];
    float* out = (float*)d_out;

    fused_kernel<<<3072, 256>>>(v_rel, w1, b1, bn_gamma, bn_beta, bn_mean,
                                bn_var, w2, b2, out);
}